// round 9
// baseline (speedup 1.0000x reference)
#include <cuda_runtime.h>
#include <cuda_bf16.h>
#include <cuda_fp16.h>
#include <cstdint>

// ---------------------------------------------------------------------------
// EarlyFusionGRU: two biGRUs (B=256, T=512, H=128) + fusion MLP + 2 heads.
// Backward direction contributes only hb_seq[0] = ONE GRU step from h0=0 on
// x[:, T-1]. Forward recurrence AND input projection on HMMA (mma.sync).
// R9: proj C tiles staged in SMEM -> fully coalesced stores; rec as R8.
// ---------------------------------------------------------------------------

#define B 256
#define T 512
#define H 128
#define G3 384   // 3*H
typedef unsigned long long ull;

static __device__ float d_pre_g[(size_t)B * T * G3];   // fwd input projections (g net)
static __device__ float d_pre_a[(size_t)B * T * G3];   // fwd input projections (a net)
static __device__ float d_WiT[2][64 * G3];             // transposed+padded fwd input weights
static __device__ float d_hcat[(size_t)B * 512];       // [hg_f | hg_b | ha_f | ha_b]

__device__ __forceinline__ float sigmoidf_(float x) { return 1.0f / (1.0f + expf(-x)); }
__device__ __forceinline__ float tanh_ap(float x) {
    float y; asm("tanh.approx.f32 %0, %1;" : "=f"(y) : "f"(x)); return y;
}
__device__ __forceinline__ float sig_ap(float x) {
    return fmaf(tanh_ap(0.5f * x), 0.5f, 0.5f);
}

__device__ __forceinline__ uint32_t pkh2(float a, float b) {
    __half2 h = __floats2half2_rn(a, b);
    return *(uint32_t*)&h;
}
// split float2 into fp16 hi-pair and fp16 lo-pair
__device__ __forceinline__ void split2(float2 v, uint32_t& hi, uint32_t& lo) {
    float hx = __half2float(__float2half_rn(v.x));
    float hy = __half2float(__float2half_rn(v.y));
    hi = pkh2(hx, hy);
    lo = pkh2(v.x - hx, v.y - hy);
}
__device__ __forceinline__ void mma16816(float* c, const uint32_t* a, uint32_t b0, uint32_t b1) {
    asm volatile(
        "mma.sync.aligned.m16n8k16.row.col.f32.f16.f16.f32 "
        "{%0,%1,%2,%3}, {%4,%5,%6,%7}, {%8,%9}, {%0,%1,%2,%3};"
        : "+f"(c[0]), "+f"(c[1]), "+f"(c[2]), "+f"(c[3])
        : "r"(a[0]), "r"(a[1]), "r"(a[2]), "r"(a[3]), "r"(b0), "r"(b1));
}
__device__ __forceinline__ uint32_t smem_u32(const void* p) {
    uint32_t a; asm("{ .reg .u64 t; cvta.to.shared.u64 t, %1; cvt.u32.u64 %0, t; }" : "=r"(a) : "l"(p));
    return a;
}
__device__ __forceinline__ void cpasync16(uint32_t dst, const void* src) {
    asm volatile("cp.async.ca.shared.global [%0], [%1], 16;" :: "r"(dst), "l"(src));
}
#define CP_COMMIT() asm volatile("cp.async.commit_group;" ::: "memory")
#define CP_WAIT1()  asm volatile("cp.async.wait_group 1;" ::: "memory")

// ---- transpose fwd input weights into [k][j] layout, zero-pad k to 64 ------
__global__ void tr_kernel(const float* __restrict__ g_wif, const float* __restrict__ a_wif) {
    int net = blockIdx.x;
    const float* Wi = net ? a_wif : g_wif;
    int I = net ? 64 : 63;
    int j = threadIdx.x;  // 0..383
    for (int k = 0; k < 64; k++)
        d_WiT[net][k * G3 + j] = (k < I) ? Wi[j * I + k] : 0.0f;
}

// ---- input projection on HMMA, SMEM-staged coalesced stores ----------------
// P[n][j] = X[n][64] @ WiT[64][384] + bi,  n = t*B + b (exactly pre's layout).
#define CPITCH 388   // f32 pitch for C stage (388 % 32 == 4 -> conflict-free rows)
__global__ __launch_bounds__(384) void proj_mma_kernel(
    const float* __restrict__ g_x, const float* __restrict__ a_x,
    const float* __restrict__ g_bi, const float* __restrict__ a_bi) {
    int net = blockIdx.y;
    int n0 = blockIdx.x * 128;
    const float* x = net ? a_x : g_x;
    int I = net ? 64 : 63;
    float* pre = net ? d_pre_a : d_pre_g;
    const float* bi = net ? a_bi : g_bi;

    extern __shared__ char dynsm[];
    __half (*Xh)[72] = (__half(*)[72])dynsm;                  // 128x72 half = 18432 B
    __half (*Xl)[72] = (__half(*)[72])(dynsm + 18432);        // 18432 B
    float* Csh = (float*)(dynsm + 36864);                     // 16 x CPITCH f32

    int tid = threadIdx.x;
    int wid = tid >> 5, lane = tid & 31;
    int qr = lane >> 2, qc = lane & 3;
    int J = wid * 32;

    // B-fragments (W), persistent: hi and lo terms
    uint32_t BH_[4][4][2], BL_[4][4][2];
    {
        const float* wt = d_WiT[net];
#pragma unroll
        for (int jt = 0; jt < 4; jt++) {
            int j = J + jt * 8 + qr;
#pragma unroll
            for (int ks = 0; ks < 4; ks++) {
#pragma unroll
                for (int r = 0; r < 2; r++) {
                    int k = ks * 16 + qc * 2 + r * 8;
                    float w0 = wt[k * G3 + j];
                    float w1 = wt[(k + 1) * G3 + j];
                    split2(make_float2(w0, w1), BH_[jt][ks][r], BL_[jt][ks][r]);
                }
            }
        }
    }
    float bj0[4], bj1[4];
#pragma unroll
    for (int jt = 0; jt < 4; jt++) {
        bj0[jt] = bi[J + jt * 8 + 2 * qc];
        bj1[jt] = bi[J + jt * 8 + 2 * qc + 1];
    }

    // load X tile [128][64] -> split into Xh/Xl
    for (int idx = tid; idx < 128 * 64; idx += 384) {
        int r = idx >> 6, k = idx & 63;
        int n = n0 + r;
        int t = n >> 8, b = n & 255;
        float v = (k < I) ? x[((size_t)b * T + t) * I + k] : 0.0f;
        __half hv = __float2half_rn(v);
        Xh[r][k] = hv;
        Xl[r][k] = __float2half_rn(v - __half2float(hv));
    }
    __syncthreads();

#pragma unroll 1
    for (int mt = 0; mt < 8; mt++) {
        float c[4][4];
#pragma unroll
        for (int jt = 0; jt < 4; jt++) {
            c[jt][0] = bj0[jt]; c[jt][1] = bj1[jt];
            c[jt][2] = bj0[jt]; c[jt][3] = bj1[jt];
        }
#pragma unroll
        for (int ks = 0; ks < 4; ks++) {
            int row = mt * 16 + qr;
            const __half* ph = &Xh[row][ks * 16 + qc * 2];
            const __half* pl = &Xl[row][ks * 16 + qc * 2];
            uint32_t Ah[4], Al[4];
            Ah[0] = *(const uint32_t*)ph;
            Ah[1] = *(const uint32_t*)(ph + 8 * 72);
            Ah[2] = *(const uint32_t*)(ph + 8);
            Ah[3] = *(const uint32_t*)(ph + 8 * 72 + 8);
            Al[0] = *(const uint32_t*)pl;
            Al[1] = *(const uint32_t*)(pl + 8 * 72);
            Al[2] = *(const uint32_t*)(pl + 8);
            Al[3] = *(const uint32_t*)(pl + 8 * 72 + 8);
#pragma unroll
            for (int jt = 0; jt < 4; jt++) {
                mma16816(c[jt], Ah, BH_[jt][ks][0], BH_[jt][ks][1]);
                mma16816(c[jt], Al, BH_[jt][ks][0], BH_[jt][ks][1]);
                mma16816(c[jt], Ah, BL_[jt][ks][0], BL_[jt][ks][1]);
            }
        }
        // stage C tile into SMEM
#pragma unroll
        for (int jt = 0; jt < 4; jt++) {
            int j0 = J + jt * 8 + 2 * qc;
            *(float2*)&Csh[qr * CPITCH + j0]       = make_float2(c[jt][0], c[jt][1]);
            *(float2*)&Csh[(qr + 8) * CPITCH + j0] = make_float2(c[jt][2], c[jt][3]);
        }
        __syncthreads();
        // coalesced copy-out: 16 rows x 384 cols, float2 per thread slot
        for (int idx = tid; idx < 16 * 192; idx += 384) {
            int r = idx / 192, c2 = idx % 192;
            float2 v = *(const float2*)&Csh[r * CPITCH + 2 * c2];
            *(float2*)(pre + (size_t)(n0 + mt * 16 + r) * G3 + 2 * c2) = v;
        }
        __syncthreads();
    }
}

// ---- forward GRU recurrence on HMMA (unchanged from R8) --------------------
__global__ __launch_bounds__(512, 1) void rec_mma_kernel(
    const float* __restrict__ g_wh, const float* __restrict__ g_bh,
    const float* __restrict__ a_wh, const float* __restrict__ a_bh) {
    int net = blockIdx.y;
    int b0 = blockIdx.x * 8;
    const float* pre = net ? d_pre_a : d_pre_g;
    const float* Wh  = net ? a_wh : g_wh;
    const float* bh  = net ? a_bh : g_bh;

    int tid = threadIdx.x;
    int wid = tid >> 5;
    int lane = tid & 31;
    int qr = lane >> 2;
    int qc = lane & 3;
    int mgroup = wid >> 1;  // 0..7 -> rows [mgroup*48, +48)
    int khalf = wid & 1;    // 0 = hi term, 1 = lo term

    extern __shared__ char dynsm[];
    __half (*Bh)[136] = (__half(*)[136])dynsm;                       // 2176 B
    float (*Dsh)[384][10] = (float(*)[384][10])(dynsm + 2304);       // 30720 B
    float* xslab = (float*)(dynsm + 2304 + 30720);                   // 24576 B
    uint32_t xslab_u32 = smem_u32(xslab);

    // register-resident A fragments: this warp's term only
    uint32_t A[3][8][4];
#pragma unroll
    for (int mt = 0; mt < 3; mt++) {
        int R = (mgroup * 3 + mt) * 16;
        int r0 = R + qr, r1 = r0 + 8;
        const float2* w0p = (const float2*)(Wh + (size_t)r0 * 128);
        const float2* w1p = (const float2*)(Wh + (size_t)r1 * 128);
#pragma unroll
        for (int kb = 0; kb < 8; kb++) {
            int ci = kb * 8 + qc;
            float2 e00 = w0p[ci], e10 = w1p[ci];
            float2 e01 = w0p[ci + 4], e11 = w1p[ci + 4];
            uint32_t hi, lo;
            split2(e00, hi, lo); A[mt][kb][0] = khalf ? lo : hi;
            split2(e10, hi, lo); A[mt][kb][1] = khalf ? lo : hi;
            split2(e01, hi, lo); A[mt][kb][2] = khalf ? lo : hi;
            split2(e11, hi, lo); A[mt][kb][3] = khalf ? lo : hi;
        }
    }

    // zero B tile (h0 = 0)
    for (int i = tid; i < 8 * 136 / 2; i += 512)
        ((uint32_t*)Bh)[i] = 0u;

    // activation bookkeeping: thread owns (bL, jj) and (bL+4, jj)
    int bL = tid >> 7;            // 0..3
    int jj = tid & 127;
    float br = bh[jj], bz = bh[128 + jj], bn = bh[256 + jj];

    float h0v = 0.0f, h1v = 0.0f;

    // prologue: stage x slab for t = 0 into buffer 0
    {
        const float* src = d_pre_g;  // placeholder, replaced below
        src = pre + (size_t)b0 * G3;
        for (int i = tid; i < 768; i += 512)
            cpasync16(xslab_u32 + i * 16, (const char*)src + i * 16);
        CP_COMMIT();
    }

    const __half* BhF = &Bh[0][0];
    __syncthreads();

#pragma unroll 1
    for (int t = 0; t < T; t++) {
        // stage x slab for step t+1 into the other buffer
        {
            int tn = (t + 1 < T) ? (t + 1) : t;
            const float* src = pre + (size_t)tn * (B * G3) + (size_t)b0 * G3;
            uint32_t dst = xslab_u32 + ((t + 1) & 1) * 12288;
            for (int i = tid; i < 768; i += 512)
                cpasync16(dst + i * 16, (const char*)src + i * 16);
            CP_COMMIT();
        }

        // MMA phase: two independent accumulators per mt (kb parity)
        float c0[3][4], c1[3][4];
#pragma unroll
        for (int mt = 0; mt < 3; mt++) {
#pragma unroll
            for (int r = 0; r < 4; r++) { c0[mt][r] = 0.0f; c1[mt][r] = 0.0f; }
        }
#pragma unroll
        for (int kb = 0; kb < 8; kb += 2) {
            int koff = qr * 136 + kb * 16 + qc * 2;
            uint32_t bf0 = *(const uint32_t*)(BhF + koff);
            uint32_t bf1 = *(const uint32_t*)(BhF + koff + 8);
            uint32_t bf2 = *(const uint32_t*)(BhF + koff + 16);
            uint32_t bf3 = *(const uint32_t*)(BhF + koff + 24);
#pragma unroll
            for (int mt = 0; mt < 3; mt++) {
                mma16816(c0[mt], A[mt][kb], bf0, bf1);
                mma16816(c1[mt], A[mt][kb + 1], bf2, bf3);
            }
        }
#pragma unroll
        for (int mt = 0; mt < 3; mt++) {
            int R = (mgroup * 3 + mt) * 16;
            *(float2*)&Dsh[khalf][R + qr][2 * qc] =
                make_float2(c0[mt][0] + c1[mt][0], c0[mt][1] + c1[mt][1]);
            *(float2*)&Dsh[khalf][R + qr + 8][2 * qc] =
                make_float2(c0[mt][2] + c1[mt][2], c0[mt][3] + c1[mt][3]);
        }
        CP_WAIT1();              // slab t resident (slab t+1 still in flight)
        __syncthreads();

        // activation phase: 2 (batch, jj) entries per thread; x from SMEM
        const float* xs = xslab + (t & 1) * 3072;
        {
            int bb = bL;
            const float* xp = xs + bb * 384 + jj;
            float dr = Dsh[0][jj][bb]       + Dsh[1][jj][bb];
            float dz = Dsh[0][jj + 128][bb] + Dsh[1][jj + 128][bb];
            float dn = Dsh[0][jj + 256][bb] + Dsh[1][jj + 256][bb];
            float r = sig_ap(xp[0] + br + dr);
            float z = sig_ap(xp[128] + bz + dz);
            float n = tanh_ap(fmaf(r, bn + dn, xp[256]));
            h0v = n + z * (h0v - n);
            Bh[bb][jj] = __float2half_rn(h0v);
        }
        {
            int bb = bL + 4;
            const float* xp = xs + bb * 384 + jj;
            float dr = Dsh[0][jj][bb]       + Dsh[1][jj][bb];
            float dz = Dsh[0][jj + 128][bb] + Dsh[1][jj + 128][bb];
            float dn = Dsh[0][jj + 256][bb] + Dsh[1][jj + 256][bb];
            float r = sig_ap(xp[0] + br + dr);
            float z = sig_ap(xp[128] + bz + dz);
            float n = tanh_ap(fmaf(r, bn + dn, xp[256]));
            h1v = n + z * (h1v - n);
            Bh[bb][jj] = __float2half_rn(h1v);
        }
        __syncthreads();
    }

    // write final forward h
    {
        int off = net ? 256 : 0;
        d_hcat[(size_t)(b0 + bL) * 512 + off + jj]     = h0v;
        d_hcat[(size_t)(b0 + bL + 4) * 512 + off + jj] = h1v;
    }
}

// ---- backward direction = ONE GRU step from h0=0 on x[:, T-1] --------------
__global__ __launch_bounds__(128) void bwd_kernel(
    const float* __restrict__ g_x, const float* __restrict__ a_x,
    const float* __restrict__ g_wib, const float* __restrict__ g_bib, const float* __restrict__ g_bhb,
    const float* __restrict__ a_wib, const float* __restrict__ a_bib, const float* __restrict__ a_bhb) {
    int b = blockIdx.x;
    int net = blockIdx.y;
    const float* x  = net ? a_x : g_x;
    int I           = net ? 64 : 63;
    const float* Wi = net ? a_wib : g_wib;
    const float* bi = net ? a_bib : g_bib;
    const float* bv = net ? a_bhb : g_bhb;

    __shared__ float xrow[64];
    int u = threadIdx.x;  // 0..127
    if (u < 64) xrow[u] = (u < I) ? x[(size_t)b * T * I + (size_t)(T - 1) * I + u] : 0.0f;
    __syncthreads();

    float s[3];
#pragma unroll
    for (int g = 0; g < 3; g++) {
        const float* wrow = Wi + (size_t)(g * 128 + u) * I;
        float acc = bi[g * 128 + u];
        for (int k = 0; k < I; k++) acc += wrow[k] * xrow[k];
        s[g] = acc;
    }
    float r = sigmoidf_(s[0] + bv[u]);
    float z = sigmoidf_(s[1] + bv[128 + u]);
    float n = tanhf(s[2] + r * bv[256 + u]);
    float hb = (1.0f - z) * n;  // + z*h0, h0 = 0

    int off = net ? 256 : 0;
    d_hcat[(size_t)b * 512 + off + 128 + u] = hb;
}

// ---- fusion MLP (512->256->128 relu) + heads (20, 30) ----------------------
__global__ __launch_bounds__(256) void mlp_kernel(
    const float* __restrict__ w1, const float* __restrict__ b1,
    const float* __restrict__ w2, const float* __restrict__ b2,
    const float* __restrict__ wm, const float* __restrict__ bm,
    const float* __restrict__ wa, const float* __restrict__ ba,
    float* __restrict__ out) {
    int b = blockIdx.x;
    __shared__ float hin[512];
    __shared__ float h1[256];
    __shared__ float h2[128];
    int t = threadIdx.x;
    hin[t]       = d_hcat[(size_t)b * 512 + t];
    hin[t + 256] = d_hcat[(size_t)b * 512 + 256 + t];
    __syncthreads();
    {
        float acc = b1[t];
        const float* wr = w1 + (size_t)t * 512;
#pragma unroll 8
        for (int k = 0; k < 512; k++) acc += wr[k] * hin[k];
        h1[t] = fmaxf(acc, 0.0f);
    }
    __syncthreads();
    if (t < 128) {
        float acc = b2[t];
        const float* wr = w2 + (size_t)t * 256;
#pragma unroll 8
        for (int k = 0; k < 256; k++) acc += wr[k] * h1[k];
        h2[t] = fmaxf(acc, 0.0f);
    }
    __syncthreads();
    if (t < 20) {
        float acc = bm[t];
        const float* wr = wm + (size_t)t * 128;
#pragma unroll 8
        for (int k = 0; k < 128; k++) acc += wr[k] * h2[k];
        out[(size_t)b * 20 + t] = acc;                       // lm
    } else if (t < 50) {
        int q = t - 20;
        float acc = ba[q];
        const float* wr = wa + (size_t)q * 128;
#pragma unroll 8
        for (int k = 0; k < 128; k++) acc += wr[k] * h2[k];
        out[5120 + (size_t)b * 30 + q] = acc;                // la (after 256*20 lm)
    }
}

extern "C" void kernel_launch(void* const* d_in, const int* in_sizes, int n_in,
                              void* d_out, int out_size) {
    const float* g_seq  = (const float*)d_in[0];
    const float* a_seq  = (const float*)d_in[1];
    const float* g_wif  = (const float*)d_in[2];
    const float* g_whf  = (const float*)d_in[3];
    const float* g_bif  = (const float*)d_in[4];
    const float* g_bhf  = (const float*)d_in[5];
    const float* g_wib  = (const float*)d_in[6];
    const float* g_bib  = (const float*)d_in[8];
    const float* g_bhb  = (const float*)d_in[9];
    const float* a_wif  = (const float*)d_in[10];
    const float* a_whf  = (const float*)d_in[11];
    const float* a_bif  = (const float*)d_in[12];
    const float* a_bhf  = (const float*)d_in[13];
    const float* a_wib  = (const float*)d_in[14];
    const float* a_bib  = (const float*)d_in[16];
    const float* a_bhb  = (const float*)d_in[17];
    const float* fuse_w1 = (const float*)d_in[18];
    const float* fuse_b1 = (const float*)d_in[19];
    const float* fuse_w2 = (const float*)d_in[20];
    const float* fuse_b2 = (const float*)d_in[21];
    const float* wm = (const float*)d_in[22];
    const float* bm = (const float*)d_in[23];
    const float* wa = (const float*)d_in[24];
    const float* ba = (const float*)d_in[25];

    const int rec_smem  = 2304 + 30720 + 24576;          // Bh | Dsh | xslab x2
    const int proj_smem = 36864 + 16 * CPITCH * 4;       // Xh/Xl | C stage
    cudaFuncSetAttribute(rec_mma_kernel, cudaFuncAttributeMaxDynamicSharedMemorySize, rec_smem);
    cudaFuncSetAttribute(proj_mma_kernel, cudaFuncAttributeMaxDynamicSharedMemorySize, proj_smem);

    tr_kernel<<<2, 384>>>(g_wif, a_wif);
    proj_mma_kernel<<<dim3((T * B) / 128, 2), 384, proj_smem>>>(g_seq, a_seq, g_bif, a_bif);
    bwd_kernel<<<dim3(B, 2), 128>>>(g_seq, a_seq, g_wib, g_bib, g_bhb, a_wib, a_bib, a_bhb);
    rec_mma_kernel<<<dim3(B / 8, 2), 512, rec_smem>>>(g_whf, g_bhf, a_whf, a_bhf);
    mlp_kernel<<<B, 256>>>(fuse_w1, fuse_b1, fuse_w2, fuse_b2, wm, bm, wa, ba, (float*)d_out);
}

// round 10
// speedup vs baseline: 2.2443x; 2.2443x over previous
#include <cuda_runtime.h>
#include <cuda_bf16.h>
#include <cuda_fp16.h>
#include <cstdint>

// ---------------------------------------------------------------------------
// EarlyFusionGRU: two biGRUs (B=256, T=512, H=128) + fusion MLP + 2 heads.
// Backward direction contributes only hb_seq[0] = ONE GRU step from h0=0 on
// x[:, T-1]. R10: precision budget spent — pre stored fp16 (halves DRAM
// traffic both directions), rec drops the Wlo split term (half the MMAs),
// 12 MMA warps + 4 cp.async copy warps (warp specialization).
// ---------------------------------------------------------------------------

#define B 256
#define T 512
#define H 128
#define G3 384   // 3*H
typedef unsigned long long ull;

static __device__ __half d_pre_g[(size_t)B * T * G3];  // fwd input projections (fp16)
static __device__ __half d_pre_a[(size_t)B * T * G3];
static __device__ float  d_WiT[2][64 * G3];            // transposed+padded fwd input weights
static __device__ float  d_hcat[(size_t)B * 512];      // [hg_f | hg_b | ha_f | ha_b]

__device__ __forceinline__ float sigmoidf_(float x) { return 1.0f / (1.0f + expf(-x)); }
__device__ __forceinline__ float tanh_ap(float x) {
    float y; asm("tanh.approx.f32 %0, %1;" : "=f"(y) : "f"(x)); return y;
}
__device__ __forceinline__ float sig_ap(float x) {
    return fmaf(tanh_ap(0.5f * x), 0.5f, 0.5f);
}

__device__ __forceinline__ uint32_t pkh2(float a, float b) {
    __half2 h = __floats2half2_rn(a, b);
    return *(uint32_t*)&h;
}
// split float2 into fp16 hi-pair and fp16 lo-pair
__device__ __forceinline__ void split2(float2 v, uint32_t& hi, uint32_t& lo) {
    float hx = __half2float(__float2half_rn(v.x));
    float hy = __half2float(__float2half_rn(v.y));
    hi = pkh2(hx, hy);
    lo = pkh2(v.x - hx, v.y - hy);
}
__device__ __forceinline__ void mma16816(float* c, const uint32_t* a, uint32_t b0, uint32_t b1) {
    asm volatile(
        "mma.sync.aligned.m16n8k16.row.col.f32.f16.f16.f32 "
        "{%0,%1,%2,%3}, {%4,%5,%6,%7}, {%8,%9}, {%0,%1,%2,%3};"
        : "+f"(c[0]), "+f"(c[1]), "+f"(c[2]), "+f"(c[3])
        : "r"(a[0]), "r"(a[1]), "r"(a[2]), "r"(a[3]), "r"(b0), "r"(b1));
}
__device__ __forceinline__ uint32_t smem_u32(const void* p) {
    uint32_t a; asm("{ .reg .u64 t; cvta.to.shared.u64 t, %1; cvt.u32.u64 %0, t; }" : "=r"(a) : "l"(p));
    return a;
}
__device__ __forceinline__ void cpasync16(uint32_t dst, const void* src) {
    asm volatile("cp.async.ca.shared.global [%0], [%1], 16;" :: "r"(dst), "l"(src));
}
#define CP_COMMIT() asm volatile("cp.async.commit_group;" ::: "memory")
#define CP_WAIT1()  asm volatile("cp.async.wait_group 1;" ::: "memory")

// ---- transpose fwd input weights into [k][j] layout, zero-pad k to 64 ------
__global__ void tr_kernel(const float* __restrict__ g_wif, const float* __restrict__ a_wif) {
    int net = blockIdx.x;
    const float* Wi = net ? a_wif : g_wif;
    int I = net ? 64 : 63;
    int j = threadIdx.x;  // 0..383
    for (int k = 0; k < 64; k++)
        d_WiT[net][k * G3 + j] = (k < I) ? Wi[j * I + k] : 0.0f;
}

// ---- input projection on HMMA (2-term: X exact, W fp16), fp16 output -------
// P[n][j] = X[n][64] @ WiT[64][384] + bi,  n = t*B + b (exactly pre's layout).
__global__ __launch_bounds__(384) void proj_mma_kernel(
    const float* __restrict__ g_x, const float* __restrict__ a_x,
    const float* __restrict__ g_bi, const float* __restrict__ a_bi) {
    int net = blockIdx.y;
    int n0 = blockIdx.x * 128;
    const float* x = net ? a_x : g_x;
    int I = net ? 64 : 63;
    __half* pre = net ? d_pre_a : d_pre_g;
    const float* bi = net ? a_bi : g_bi;

    __shared__ __half Xh[128][72];   // X hi halves, padded pitch
    __shared__ __half Xl[128][72];   // X lo halves

    int tid = threadIdx.x;
    int wid = tid >> 5, lane = tid & 31;
    int qr = lane >> 2, qc = lane & 3;
    int J = wid * 32;

    // B-fragments (W fp16), persistent
    uint32_t BH_[4][4][2];
    {
        const float* wt = d_WiT[net];
#pragma unroll
        for (int jt = 0; jt < 4; jt++) {
            int j = J + jt * 8 + qr;
#pragma unroll
            for (int ks = 0; ks < 4; ks++) {
#pragma unroll
                for (int r = 0; r < 2; r++) {
                    int k = ks * 16 + qc * 2 + r * 8;
                    float w0 = wt[k * G3 + j];
                    float w1 = wt[(k + 1) * G3 + j];
                    BH_[jt][ks][r] = pkh2(__half2float(__float2half_rn(w0)),
                                          __half2float(__float2half_rn(w1)));
                }
            }
        }
    }
    float bj0[4], bj1[4];
#pragma unroll
    for (int jt = 0; jt < 4; jt++) {
        bj0[jt] = bi[J + jt * 8 + 2 * qc];
        bj1[jt] = bi[J + jt * 8 + 2 * qc + 1];
    }

    // load X tile [128][64] -> split into Xh/Xl
    for (int idx = tid; idx < 128 * 64; idx += 384) {
        int r = idx >> 6, k = idx & 63;
        int n = n0 + r;
        int t = n >> 8, b = n & 255;
        float v = (k < I) ? x[((size_t)b * T + t) * I + k] : 0.0f;
        __half hv = __float2half_rn(v);
        Xh[r][k] = hv;
        Xl[r][k] = __float2half_rn(v - __half2float(hv));
    }
    __syncthreads();

#pragma unroll 1
    for (int mt = 0; mt < 8; mt++) {
        float c[4][4];
#pragma unroll
        for (int jt = 0; jt < 4; jt++) {
            c[jt][0] = bj0[jt]; c[jt][1] = bj1[jt];
            c[jt][2] = bj0[jt]; c[jt][3] = bj1[jt];
        }
#pragma unroll
        for (int ks = 0; ks < 4; ks++) {
            int row = mt * 16 + qr;
            const __half* ph = &Xh[row][ks * 16 + qc * 2];
            const __half* pl = &Xl[row][ks * 16 + qc * 2];
            uint32_t Ah[4], Al[4];
            Ah[0] = *(const uint32_t*)ph;
            Ah[1] = *(const uint32_t*)(ph + 8 * 72);
            Ah[2] = *(const uint32_t*)(ph + 8);
            Ah[3] = *(const uint32_t*)(ph + 8 * 72 + 8);
            Al[0] = *(const uint32_t*)pl;
            Al[1] = *(const uint32_t*)(pl + 8 * 72);
            Al[2] = *(const uint32_t*)(pl + 8);
            Al[3] = *(const uint32_t*)(pl + 8 * 72 + 8);
#pragma unroll
            for (int jt = 0; jt < 4; jt++) {
                mma16816(c[jt], Ah, BH_[jt][ks][0], BH_[jt][ks][1]);
                mma16816(c[jt], Al, BH_[jt][ks][0], BH_[jt][ks][1]);
            }
        }
        // store fp16: rows n0+mt*16+qr (+8), cols J+jt*8+2qc (+1)
#pragma unroll
        for (int jt = 0; jt < 4; jt++) {
            int j0 = J + jt * 8 + 2 * qc;
            __half* p0 = pre + (size_t)(n0 + mt * 16 + qr) * G3 + j0;
            *(__half2*)p0 = __floats2half2_rn(c[jt][0], c[jt][1]);
            *(__half2*)(p0 + (size_t)8 * G3) = __floats2half2_rn(c[jt][2], c[jt][3]);
        }
    }
}

// ---- forward GRU recurrence on HMMA ----------------------------------------
// Single W term (fp16). 512 threads = 12 MMA warps (2 m16-tiles each, 2
// independent k-chains of depth 4) + 4 copy warps staging the fp16 x-slab
// via cp.async double buffer. Activation: all 512 threads, 2 entries each.
__global__ __launch_bounds__(512, 1) void rec_mma_kernel(
    const float* __restrict__ g_wh, const float* __restrict__ g_bh,
    const float* __restrict__ a_wh, const float* __restrict__ a_bh) {
    int net = blockIdx.y;
    int b0 = blockIdx.x * 8;
    const __half* pre = net ? d_pre_a : d_pre_g;
    const float* Wh  = net ? a_wh : g_wh;
    const float* bh  = net ? a_bh : g_bh;

    int tid = threadIdx.x;
    int wid = tid >> 5;
    int lane = tid & 31;
    int qr = lane >> 2;
    int qc = lane & 3;

    // dynamic smem: Bh[8][136] half | Dsh[384][10] f32 | xslab[2][3072] half
    extern __shared__ char dynsm[];
    __half (*Bh)[136] = (__half(*)[136])dynsm;                  // 2176 B (pad 2304)
    float (*Dsh)[10] = (float(*)[10])(dynsm + 2304);            // 15360 B
    __half* xslab = (__half*)(dynsm + 2304 + 15360);            // 12288 B
    uint32_t xslab_u32 = smem_u32(xslab);

    // MMA warps (0-11): register-resident A fragments, W fp16 single term
    uint32_t A[2][8][4];
    if (wid < 12) {
#pragma unroll
        for (int mt = 0; mt < 2; mt++) {
            int R = (wid * 2 + mt) * 16;
            int r0 = R + qr, r1 = r0 + 8;
            const float2* w0p = (const float2*)(Wh + (size_t)r0 * 128);
            const float2* w1p = (const float2*)(Wh + (size_t)r1 * 128);
#pragma unroll
            for (int kb = 0; kb < 8; kb++) {
                int ci = kb * 8 + qc;
                float2 e00 = w0p[ci], e10 = w1p[ci];
                float2 e01 = w0p[ci + 4], e11 = w1p[ci + 4];
                A[mt][kb][0] = pkh2(e00.x, e00.y);
                A[mt][kb][1] = pkh2(e10.x, e10.y);
                A[mt][kb][2] = pkh2(e01.x, e01.y);
                A[mt][kb][3] = pkh2(e11.x, e11.y);
            }
        }
    }

    // zero B tile (h0 = 0)
    for (int i = tid; i < 8 * 136 / 2; i += 512)
        ((uint32_t*)Bh)[i] = 0u;

    // activation bookkeeping: thread owns (bL, jj) and (bL+4, jj)
    int bL = tid >> 7;            // 0..3
    int jj = tid & 127;
    float br = bh[jj], bz = bh[128 + jj], bn = bh[256 + jj];

    float h0v = 0.0f, h1v = 0.0f;

    // prologue: copy warps stage x slab (fp16, 6144 B) for t = 0 into buffer 0
    if (wid >= 12) {
        const __half* src = pre + (size_t)b0 * G3;
        for (int i = tid - 384; i < 384; i += 128)
            cpasync16(xslab_u32 + i * 16, (const char*)src + i * 16);
        CP_COMMIT();
    }

    const __half* BhF = &Bh[0][0];
    __syncthreads();

#pragma unroll 1
    for (int t = 0; t < T; t++) {
        if (wid >= 12) {
            // copy warps: stage x slab for step t+1 into the other buffer
            int tn = (t + 1 < T) ? (t + 1) : t;
            const __half* src = pre + (size_t)tn * (B * G3) + (size_t)b0 * G3;
            uint32_t dst = xslab_u32 + ((t + 1) & 1) * 6144;
            for (int i = tid - 384; i < 384; i += 128)
                cpasync16(dst + i * 16, (const char*)src + i * 16);
            CP_COMMIT();
            CP_WAIT1();          // slab t resident (slab t+1 in flight)
        } else {
            // MMA warps: 2 m-tiles, 2 independent k-chains each (depth 4)
            float c0[2][4], c1[2][4];
#pragma unroll
            for (int mt = 0; mt < 2; mt++) {
#pragma unroll
                for (int r = 0; r < 4; r++) { c0[mt][r] = 0.0f; c1[mt][r] = 0.0f; }
            }
#pragma unroll
            for (int kb = 0; kb < 8; kb += 2) {
                int koff = qr * 136 + kb * 16 + qc * 2;
                uint32_t bf0 = *(const uint32_t*)(BhF + koff);
                uint32_t bf1 = *(const uint32_t*)(BhF + koff + 8);
                uint32_t bf2 = *(const uint32_t*)(BhF + koff + 16);
                uint32_t bf3 = *(const uint32_t*)(BhF + koff + 24);
#pragma unroll
                for (int mt = 0; mt < 2; mt++) {
                    mma16816(c0[mt], A[mt][kb], bf0, bf1);
                    mma16816(c1[mt], A[mt][kb + 1], bf2, bf3);
                }
            }
#pragma unroll
            for (int mt = 0; mt < 2; mt++) {
                int R = (wid * 2 + mt) * 16;
                *(float2*)&Dsh[R + qr][2 * qc] =
                    make_float2(c0[mt][0] + c1[mt][0], c0[mt][1] + c1[mt][1]);
                *(float2*)&Dsh[R + qr + 8][2 * qc] =
                    make_float2(c0[mt][2] + c1[mt][2], c0[mt][3] + c1[mt][3]);
            }
        }
        __syncthreads();

        // activation phase: 2 (batch, jj) entries per thread; x fp16 from SMEM
        const __half* xs = xslab + (t & 1) * 3072;
        {
            int bb = bL;
            const __half* xp = xs + bb * 384 + jj;
            float r = sig_ap(__half2float(xp[0]) + br + Dsh[jj][bb]);
            float z = sig_ap(__half2float(xp[128]) + bz + Dsh[jj + 128][bb]);
            float n = tanh_ap(fmaf(r, bn + Dsh[jj + 256][bb], __half2float(xp[256])));
            h0v = n + z * (h0v - n);
            Bh[bb][jj] = __float2half_rn(h0v);
        }
        {
            int bb = bL + 4;
            const __half* xp = xs + bb * 384 + jj;
            float r = sig_ap(__half2float(xp[0]) + br + Dsh[jj][bb]);
            float z = sig_ap(__half2float(xp[128]) + bz + Dsh[jj + 128][bb]);
            float n = tanh_ap(fmaf(r, bn + Dsh[jj + 256][bb], __half2float(xp[256])));
            h1v = n + z * (h1v - n);
            Bh[bb][jj] = __float2half_rn(h1v);
        }
        __syncthreads();
    }

    // write final forward h
    {
        int off = net ? 256 : 0;
        d_hcat[(size_t)(b0 + bL) * 512 + off + jj]     = h0v;
        d_hcat[(size_t)(b0 + bL + 4) * 512 + off + jj] = h1v;
    }
}

// ---- backward direction = ONE GRU step from h0=0 on x[:, T-1] --------------
__global__ __launch_bounds__(128) void bwd_kernel(
    const float* __restrict__ g_x, const float* __restrict__ a_x,
    const float* __restrict__ g_wib, const float* __restrict__ g_bib, const float* __restrict__ g_bhb,
    const float* __restrict__ a_wib, const float* __restrict__ a_bib, const float* __restrict__ a_bhb) {
    int b = blockIdx.x;
    int net = blockIdx.y;
    const float* x  = net ? a_x : g_x;
    int I           = net ? 64 : 63;
    const float* Wi = net ? a_wib : g_wib;
    const float* bi = net ? a_bib : g_bib;
    const float* bv = net ? a_bhb : g_bhb;

    __shared__ float xrow[64];
    int u = threadIdx.x;  // 0..127
    if (u < 64) xrow[u] = (u < I) ? x[(size_t)b * T * I + (size_t)(T - 1) * I + u] : 0.0f;
    __syncthreads();

    float s[3];
#pragma unroll
    for (int g = 0; g < 3; g++) {
        const float* wrow = Wi + (size_t)(g * 128 + u) * I;
        float acc = bi[g * 128 + u];
        for (int k = 0; k < I; k++) acc += wrow[k] * xrow[k];
        s[g] = acc;
    }
    float r = sigmoidf_(s[0] + bv[u]);
    float z = sigmoidf_(s[1] + bv[128 + u]);
    float n = tanhf(s[2] + r * bv[256 + u]);
    float hb = (1.0f - z) * n;  // + z*h0, h0 = 0

    int off = net ? 256 : 0;
    d_hcat[(size_t)b * 512 + off + 128 + u] = hb;
}

// ---- fusion MLP (512->256->128 relu) + heads (20, 30) ----------------------
__global__ __launch_bounds__(256) void mlp_kernel(
    const float* __restrict__ w1, const float* __restrict__ b1,
    const float* __restrict__ w2, const float* __restrict__ b2,
    const float* __restrict__ wm, const float* __restrict__ bm,
    const float* __restrict__ wa, const float* __restrict__ ba,
    float* __restrict__ out) {
    int b = blockIdx.x;
    __shared__ float hin[512];
    __shared__ float h1[256];
    __shared__ float h2[128];
    int t = threadIdx.x;
    hin[t]       = d_hcat[(size_t)b * 512 + t];
    hin[t + 256] = d_hcat[(size_t)b * 512 + 256 + t];
    __syncthreads();
    {
        float acc = b1[t];
        const float* wr = w1 + (size_t)t * 512;
#pragma unroll 8
        for (int k = 0; k < 512; k++) acc += wr[k] * hin[k];
        h1[t] = fmaxf(acc, 0.0f);
    }
    __syncthreads();
    if (t < 128) {
        float acc = b2[t];
        const float* wr = w2 + (size_t)t * 256;
#pragma unroll 8
        for (int k = 0; k < 256; k++) acc += wr[k] * h1[k];
        h2[t] = fmaxf(acc, 0.0f);
    }
    __syncthreads();
    if (t < 20) {
        float acc = bm[t];
        const float* wr = wm + (size_t)t * 128;
#pragma unroll 8
        for (int k = 0; k < 128; k++) acc += wr[k] * h2[k];
        out[(size_t)b * 20 + t] = acc;                       // lm
    } else if (t < 50) {
        int q = t - 20;
        float acc = ba[q];
        const float* wr = wa + (size_t)q * 128;
#pragma unroll 8
        for (int k = 0; k < 128; k++) acc += wr[k] * h2[k];
        out[5120 + (size_t)b * 30 + q] = acc;                // la (after 256*20 lm)
    }
}

extern "C" void kernel_launch(void* const* d_in, const int* in_sizes, int n_in,
                              void* d_out, int out_size) {
    const float* g_seq  = (const float*)d_in[0];
    const float* a_seq  = (const float*)d_in[1];
    const float* g_wif  = (const float*)d_in[2];
    const float* g_whf  = (const float*)d_in[3];
    const float* g_bif  = (const float*)d_in[4];
    const float* g_bhf  = (const float*)d_in[5];
    const float* g_wib  = (const float*)d_in[6];
    const float* g_bib  = (const float*)d_in[8];
    const float* g_bhb  = (const float*)d_in[9];
    const float* a_wif  = (const float*)d_in[10];
    const float* a_whf  = (const float*)d_in[11];
    const float* a_bif  = (const float*)d_in[12];
    const float* a_bhf  = (const float*)d_in[13];
    const float* a_wib  = (const float*)d_in[14];
    const float* a_bib  = (const float*)d_in[16];
    const float* a_bhb  = (const float*)d_in[17];
    const float* fuse_w1 = (const float*)d_in[18];
    const float* fuse_b1 = (const float*)d_in[19];
    const float* fuse_w2 = (const float*)d_in[20];
    const float* fuse_b2 = (const float*)d_in[21];
    const float* wm = (const float*)d_in[22];
    const float* bm = (const float*)d_in[23];
    const float* wa = (const float*)d_in[24];
    const float* ba = (const float*)d_in[25];

    const int rec_smem = 2304 + 15360 + 12288;   // Bh | Dsh | xslab x2 (fp16)
    cudaFuncSetAttribute(rec_mma_kernel, cudaFuncAttributeMaxDynamicSharedMemorySize, rec_smem);

    tr_kernel<<<2, 384>>>(g_wif, a_wif);
    proj_mma_kernel<<<dim3((T * B) / 128, 2), 384>>>(g_seq, a_seq, g_bif, a_bif);
    bwd_kernel<<<dim3(B, 2), 128>>>(g_seq, a_seq, g_wib, g_bib, g_bhb, a_wib, a_bib, a_bhb);
    rec_mma_kernel<<<dim3(B / 8, 2), 512, rec_smem>>>(g_whf, g_bhf, a_whf, a_bhf);
    mlp_kernel<<<B, 256>>>(fuse_w1, fuse_b1, fuse_w2, fuse_b2, wm, bm, wa, ba, (float*)d_out);
}